// round 6
// baseline (speedup 1.0000x reference)
#include <cuda_runtime.h>
#include <cstdint>

// Problem constants
#define MTOT 16384      // 2 streams * B(4) * L(2048)
#define HALF_M 8192
#define DIM 512
#define PF 2048
#define NB 4
#define NH 8
#define DH 64
#define LN_EPS 1e-5f

// ---------------- scratch (static device globals; no allocation) -------------
__device__ float g_X   [MTOT * DIM];   // exact stacked input (residual)
__device__ float g_Xr  [MTOT * DIM];   // tf32-rounded stacked input (GEMM operand)
__device__ float g_Q   [MTOT * DIM];
__device__ float g_K   [MTOT * DIM];
__device__ float g_V   [MTOT * DIM];
__device__ float g_attn[MTOT * DIM];   // rounded at qs output
__device__ float g_proj[MTOT * DIM];
__device__ float g_x1  [MTOT * DIM];   // exact (LN2 residual)
__device__ float g_x1r [MTOT * DIM];   // rounded (FF1 operand)
__device__ float g_h1  [MTOT * PF];    // rounded at FF1 epilogue
__device__ float g_ff  [MTOT * DIM];
__device__ float g_S   [NB * NH * DH * DH];
// rounded weights
__device__ float g_Wqr[DIM * DIM];
__device__ float g_Wkr[DIM * DIM];
__device__ float g_Wvr[DIM * DIM];
__device__ float g_Wor[DIM * DIM];
__device__ float g_W1r[PF * DIM];
__device__ float g_W2r[DIM * PF];

// ---------------- helpers ----------------------------------------------------
__device__ __forceinline__ uint32_t f2tf(float f) {
    uint32_t r;
    asm("cvt.rna.tf32.f32 %0, %1;" : "=r"(r) : "f"(f));
    return r;
}
__device__ __forceinline__ float roundtf(float f) { return __uint_as_float(f2tf(f)); }
__device__ __forceinline__ float4 round4(float4 v) {
    return make_float4(roundtf(v.x), roundtf(v.y), roundtf(v.z), roundtf(v.w));
}
__device__ __forceinline__ uint32_t smem_u32(const void* p) {
    uint32_t a;
    asm("{ .reg .u64 t; cvta.to.shared.u64 t, %1; cvt.u32.u64 %0, t; }" : "=r"(a) : "l"(p));
    return a;
}
__device__ __forceinline__ void mma_tf32(float& c0, float& c1, float& c2, float& c3,
                                         uint32_t a0, uint32_t a1, uint32_t a2, uint32_t a3,
                                         uint32_t b0, uint32_t b1)
{
    asm volatile(
        "mma.sync.aligned.m16n8k8.row.col.f32.tf32.tf32.f32 "
        "{%0,%1,%2,%3}, {%4,%5,%6,%7}, {%8,%9}, {%0,%1,%2,%3};"
        : "+f"(c0), "+f"(c1), "+f"(c2), "+f"(c3)
        : "r"(a0), "r"(a1), "r"(a2), "r"(a3), "r"(b0), "r"(b1));
}
__device__ __forceinline__ void ldsm4(uint32_t& r0, uint32_t& r1, uint32_t& r2, uint32_t& r3,
                                      uint32_t addr)
{
    asm volatile("ldmatrix.sync.aligned.m8n8.x4.shared.b16 {%0,%1,%2,%3}, [%4];"
                 : "=r"(r0), "=r"(r1), "=r"(r2), "=r"(r3) : "r"(addr));
}
__device__ __forceinline__ void cp16(uint32_t saddr, const float* g) {
    asm volatile("cp.async.cg.shared.global [%0], [%1], 16;" :: "r"(saddr), "l"(g) : "memory");
}

// ---------------- weight tf32 pre-round ---------------------------------------
__global__ void wcvt_kernel(const float* __restrict__ src, float* __restrict__ dst, int n4) {
    int i = blockIdx.x * blockDim.x + threadIdx.x;
    if (i < n4)
        reinterpret_cast<float4*>(dst)[i] = round4(reinterpret_cast<const float4*>(src)[i]);
}

// ---------------- pack: exact + rounded ---------------------------------------
__global__ void pack_kernel(const float* __restrict__ a, const float* __restrict__ b) {
    int i = blockIdx.x * blockDim.x + threadIdx.x;
    const int n4 = HALF_M * DIM / 4;
    float4* X  = reinterpret_cast<float4*>(g_X);
    float4* Xr = reinterpret_cast<float4*>(g_Xr);
    if (i < n4) {
        float4 va = reinterpret_cast<const float4*>(a)[i];
        float4 vb = reinterpret_cast<const float4*>(b)[i];
        X[i] = va;            X[i + n4] = vb;
        Xr[i] = round4(va);   Xr[i + n4] = round4(vb);
    }
}

// ============ tf32 mma.sync GEMM (cp.async 3-stage, swizzled smem) ============
// C[M,N] = A[M,K] @ W[N,K]^T + bias. Operands MUST be pre-rounded to tf32.
// 128x128 CTA tile, BK=32, 256 threads (8 warps, 2x4), warp tile 64x32.
// Stage layout: 32KB = A[128x32] + W[128x32]; byte addr = row*128 + ((seg^(row&7))*16)
#define NSTAGE 3
#define STAGE_BYTES 32768

__global__ void __launch_bounds__(256)
tc_gemm_kernel(const float* __restrict__ A, const float* __restrict__ W,
               const float* __restrict__ bias, float* __restrict__ C,
               int K, int N, int relu, int rnd)
{
    extern __shared__ float smem[];

    const int tid  = threadIdx.x;
    const int wid  = tid >> 5;
    const int lane = tid & 31;
    const int g    = lane >> 2;
    const int tg   = lane & 3;
    const int wm   = wid >> 2;
    const int wn   = wid & 3;
    const int bm = blockIdx.y, bn = blockIdx.x;

    const float* Ag = A + (size_t)bm * 128 * K;
    const float* Wg = W + (size_t)bn * 128 * K;

    const uint32_t sb = smem_u32(smem);

    // cp.async mapping: idx = i*256+tid; row=idx>>3, seg=idx&7 (16B units)
    uint32_t stOff[4];
    size_t   gOff[4];
#pragma unroll
    for (int i = 0; i < 4; i++) {
        int idx = i * 256 + tid;
        int row = idx >> 3, seg = idx & 7;
        stOff[i] = (uint32_t)(row * 128 + ((seg ^ (row & 7)) << 4));
        gOff[i]  = (size_t)row * K + seg * 4;
    }

    // ldmatrix lane addressing (logical layout identical to padded version)
    const int rowA = ((lane >> 3) & 1) * 8 + (lane & 7);
    const int cA   = (lane >> 4);            // k 16B-half select
    const int rowB = ((lane >> 4) & 1) * 8 + (lane & 7);
    const int cB   = ((lane >> 3) & 1);
    const uint32_t mask = (uint32_t)(lane & 7);   // = rowA&7 = rowB&7

    uint32_t aRowOff[4], bRowOff[2];
#pragma unroll
    for (int mi = 0; mi < 4; mi++)
        aRowOff[mi] = (uint32_t)((wm * 64 + mi * 16 + rowA) * 128);
#pragma unroll
    for (int n2 = 0; n2 < 2; n2++)
        bRowOff[n2] = (uint32_t)(16384 + (wn * 32 + n2 * 16 + rowB) * 128);

    float acc[4][4][4];
#pragma unroll
    for (int mi = 0; mi < 4; mi++)
#pragma unroll
        for (int ni = 0; ni < 4; ni++)
#pragma unroll
            for (int r = 0; r < 4; r++) acc[mi][ni][r] = 0.f;

    const int NC = K >> 5;

    // prologue: stages 0,1
#pragma unroll
    for (int p = 0; p < 2; p++) {
        uint32_t st = sb + p * STAGE_BYTES;
        size_t go = (size_t)p * 32;
#pragma unroll
        for (int i = 0; i < 4; i++) {
            cp16(st + stOff[i],         Ag + gOff[i] + go);
            cp16(st + 16384 + stOff[i], Wg + gOff[i] + go);
        }
        asm volatile("cp.async.commit_group;" ::: "memory");
    }

    for (int c = 0; c < NC; ++c) {
        asm volatile("cp.async.wait_group 1;" ::: "memory");
        __syncthreads();

        // issue chunk c+2 into stage (c+2)%3 (that buffer was consumed in chunk c-1)
        if (c + 2 < NC) {
            int s2 = (c + 2) % NSTAGE;
            uint32_t st = sb + s2 * STAGE_BYTES;
            size_t go = (size_t)(c + 2) * 32;
#pragma unroll
            for (int i = 0; i < 4; i++) {
                cp16(st + stOff[i],         Ag + gOff[i] + go);
                cp16(st + 16384 + stOff[i], Wg + gOff[i] + go);
            }
        }
        asm volatile("cp.async.commit_group;" ::: "memory");

        // compute stage c%3
        const uint32_t base = sb + (c % NSTAGE) * STAGE_BYTES;
#pragma unroll
        for (int ks = 0; ks < 4; ks++) {
            uint32_t a[4][4];
#pragma unroll
            for (int mi = 0; mi < 4; mi++)
                ldsm4(a[mi][0], a[mi][1], a[mi][2], a[mi][3],
                      base + aRowOff[mi] + ((((uint32_t)(ks * 2 + cA)) ^ mask) << 4));
            uint32_t b[2][4];
#pragma unroll
            for (int n2 = 0; n2 < 2; n2++)
                ldsm4(b[n2][0], b[n2][1], b[n2][2], b[n2][3],
                      base + bRowOff[n2] + ((((uint32_t)(ks * 2 + cB)) ^ mask) << 4));
#pragma unroll
            for (int mi = 0; mi < 4; mi++)
#pragma unroll
                for (int ni = 0; ni < 4; ni++) {
                    const uint32_t b0 = (ni & 1) ? b[ni >> 1][2] : b[ni >> 1][0];
                    const uint32_t b1 = (ni & 1) ? b[ni >> 1][3] : b[ni >> 1][1];
                    mma_tf32(acc[mi][ni][0], acc[mi][ni][1], acc[mi][ni][2], acc[mi][ni][3],
                             a[mi][0], a[mi][1], a[mi][2], a[mi][3], b0, b1);
                }
        }
    }

    // ---- epilogue
    const float2* bias2 = reinterpret_cast<const float2*>(bias);
#pragma unroll
    for (int mi = 0; mi < 4; mi++) {
        int r0 = bm * 128 + wm * 64 + mi * 16 + g;
#pragma unroll
        for (int ni = 0; ni < 4; ni++) {
            int col = bn * 128 + wn * 32 + ni * 8 + 2 * tg;
            float2 bv = __ldg(&bias2[col >> 1]);
            float2 o0, o1;
            o0.x = acc[mi][ni][0] + bv.x;
            o0.y = acc[mi][ni][1] + bv.y;
            o1.x = acc[mi][ni][2] + bv.x;
            o1.y = acc[mi][ni][3] + bv.y;
            if (relu) {
                o0.x = fmaxf(o0.x, 0.f); o0.y = fmaxf(o0.y, 0.f);
                o1.x = fmaxf(o1.x, 0.f); o1.y = fmaxf(o1.y, 0.f);
            }
            if (rnd) {
                o0.x = roundtf(o0.x); o0.y = roundtf(o0.y);
                o1.x = roundtf(o1.x); o1.y = roundtf(o1.y);
            }
            *reinterpret_cast<float2*>(C + (size_t)r0 * N + col) = o0;
            *reinterpret_cast<float2*>(C + (size_t)(r0 + 8) * N + col) = o1;
        }
    }
}

// ---------------- S state: S[b,h] = K1^T V1 + K2^T V2 ------------------------
__global__ void __launch_bounds__(256)
s_kernel()
{
    const int b = blockIdx.x >> 3;
    const int h = blockIdx.x & 7;
    __shared__ float Ks[32][64];
    __shared__ float Vs[32][64];

    const int tid = threadIdx.x;
    const int te = tid & 15;
    const int td = tid >> 4;

    float acc[4][4];
#pragma unroll
    for (int i = 0; i < 4; i++)
#pragma unroll
        for (int j = 0; j < 4; j++) acc[i][j] = 0.f;

    for (int s = 0; s < 2; s++) {
        const int rb = (s * 4 + b) * 2048;
        for (int l0 = 0; l0 < 2048; l0 += 32) {
#pragma unroll
            for (int i = 0; i < 2; i++) {
                int idx = tid + i * 256;
                int l = idx >> 4;
                int ec = (idx & 15) * 4;
                size_t goff = (size_t)(rb + l0 + l) * DIM + h * DH + ec;
                *reinterpret_cast<float4*>(&Ks[l][ec]) = *reinterpret_cast<const float4*>(&g_K[goff]);
                *reinterpret_cast<float4*>(&Vs[l][ec]) = *reinterpret_cast<const float4*>(&g_V[goff]);
            }
            __syncthreads();
#pragma unroll 8
            for (int l = 0; l < 32; l++) {
                float kr[4], vr[4];
                *reinterpret_cast<float4*>(kr) = *reinterpret_cast<const float4*>(&Ks[l][te * 4]);
                *reinterpret_cast<float4*>(vr) = *reinterpret_cast<const float4*>(&Vs[l][td * 4]);
#pragma unroll
                for (int i = 0; i < 4; i++)
#pragma unroll
                    for (int j = 0; j < 4; j++)
                        acc[i][j] += kr[i] * vr[j];
            }
            __syncthreads();
        }
    }

    float* Sp = &g_S[(b * 8 + h) * DH * DH];
#pragma unroll
    for (int i = 0; i < 4; i++) {
        int e = te * 4 + i;
        *reinterpret_cast<float4*>(&Sp[e * DH + td * 4]) =
            make_float4(acc[i][0], acc[i][1], acc[i][2], acc[i][3]);
    }
}

// ---------------- Q @ S -> attn (rounded output) ------------------------------
__global__ void __launch_bounds__(256)
qs_kernel()
{
    const int h = blockIdx.y;
    const int r0 = blockIdx.x * 64;
    const int b = (r0 >> 11) & 3;

    __shared__ float Ss[64][64];
    __shared__ float Qs[64][72];

    const int tid = threadIdx.x;

    const float* Sp = &g_S[(b * 8 + h) * DH * DH];
#pragma unroll
    for (int i = 0; i < 4; i++) {
        int idx = tid + i * 256;
        reinterpret_cast<float4*>(Ss)[idx] = reinterpret_cast<const float4*>(Sp)[idx];
    }
#pragma unroll
    for (int i = 0; i < 4; i++) {
        int idx = tid + i * 256;
        int l = idx >> 4;
        int ec = (idx & 15) * 4;
        *reinterpret_cast<float4*>(&Qs[l][ec]) =
            *reinterpret_cast<const float4*>(&g_Q[(size_t)(r0 + l) * DIM + h * DH + ec]);
    }
    __syncthreads();

    const int rl = tid >> 2;
    const int d0 = (tid & 3) * 16;

    float acc[16];
#pragma unroll
    for (int j = 0; j < 16; j++) acc[j] = 0.f;

#pragma unroll 4
    for (int e = 0; e < 64; e++) {
        float q = Qs[rl][e];
#pragma unroll
        for (int j = 0; j < 16; j += 4) {
            float4 sv = *reinterpret_cast<const float4*>(&Ss[e][d0 + j]);
            acc[j + 0] += q * sv.x;
            acc[j + 1] += q * sv.y;
            acc[j + 2] += q * sv.z;
            acc[j + 3] += q * sv.w;
        }
    }

    size_t base = (size_t)(r0 + rl) * DIM + h * DH + d0;
#pragma unroll
    for (int j = 0; j < 16; j += 4) {
        *reinterpret_cast<float4*>(&g_attn[base + j]) =
            make_float4(roundtf(acc[j]), roundtf(acc[j + 1]),
                        roundtf(acc[j + 2]), roundtf(acc[j + 3]));
    }
}

// ---------------- fused residual + LayerNorm (optional rounded copy) ----------
__global__ void __launch_bounds__(128)
ln_kernel(const float* __restrict__ A, const float* __restrict__ R,
          const float* __restrict__ gamma, const float* __restrict__ beta,
          float* __restrict__ out, float* __restrict__ out2, int concat)
{
    const int row = blockIdx.x;
    const int tid = threadIdx.x;
    const int c = tid * 4;
    const size_t off = (size_t)row * DIM + c;

    float4 a = *reinterpret_cast<const float4*>(A + off);
    float4 r = *reinterpret_cast<const float4*>(R + off);
    float v0 = a.x + r.x, v1 = a.y + r.y, v2 = a.z + r.z, v3 = a.w + r.w;

    float s = v0 + v1 + v2 + v3;
    float q = v0 * v0 + v1 * v1 + v2 * v2 + v3 * v3;
#pragma unroll
    for (int o = 16; o > 0; o >>= 1) {
        s += __shfl_xor_sync(0xffffffffu, s, o);
        q += __shfl_xor_sync(0xffffffffu, q, o);
    }
    __shared__ float ss[4], sq[4];
    if ((tid & 31) == 0) { ss[tid >> 5] = s; sq[tid >> 5] = q; }
    __syncthreads();
    s = ss[0] + ss[1] + ss[2] + ss[3];
    q = sq[0] + sq[1] + sq[2] + sq[3];

    const float mean = s * (1.f / DIM);
    const float var = q * (1.f / DIM) - mean * mean;
    const float rstd = rsqrtf(var + LN_EPS);

    float4 gv = *reinterpret_cast<const float4*>(gamma + c);
    float4 bv = *reinterpret_cast<const float4*>(beta + c);
    float4 o;
    o.x = (v0 - mean) * rstd * gv.x + bv.x;
    o.y = (v1 - mean) * rstd * gv.y + bv.y;
    o.z = (v2 - mean) * rstd * gv.z + bv.z;
    o.w = (v3 - mean) * rstd * gv.w + bv.w;

    if (!concat) {
        *reinterpret_cast<float4*>(out + off) = o;
        if (out2) *reinterpret_cast<float4*>(out2 + off) = round4(o);
    } else {
        int sdx = row >> 13;
        int rem = row & 8191;
        *reinterpret_cast<float4*>(out + (size_t)rem * 1024 + sdx * 512 + c) = o;
    }
}

// ---------------- launch ------------------------------------------------------
extern "C" void kernel_launch(void* const* d_in, const int* in_sizes, int n_in,
                              void* d_out, int out_size)
{
    (void)in_sizes; (void)n_in; (void)out_size;
    const float* question = (const float*)d_in[0];
    const float* query    = (const float*)d_in[1];
    const float* Wq = (const float*)d_in[2];
    const float* bq = (const float*)d_in[3];
    const float* Wk = (const float*)d_in[4];
    const float* bk = (const float*)d_in[5];
    const float* Wv = (const float*)d_in[6];
    const float* bv = (const float*)d_in[7];
    const float* Wo = (const float*)d_in[8];
    const float* bo = (const float*)d_in[9];
    const float* ln_g = (const float*)d_in[10];
    const float* ln_b = (const float*)d_in[11];
    const float* W1 = (const float*)d_in[12];
    const float* b1 = (const float*)d_in[13];
    const float* W2 = (const float*)d_in[14];
    const float* b2 = (const float*)d_in[15];
    float* out = (float*)d_out;

    float *X, *Xr, *Q, *K, *V, *attn, *proj, *x1, *x1r, *h1, *ff;
    float *Wqr, *Wkr, *Wvr, *Wor, *W1r, *W2r;
    cudaGetSymbolAddress((void**)&X,    g_X);
    cudaGetSymbolAddress((void**)&Xr,   g_Xr);
    cudaGetSymbolAddress((void**)&Q,    g_Q);
    cudaGetSymbolAddress((void**)&K,    g_K);
    cudaGetSymbolAddress((void**)&V,    g_V);
    cudaGetSymbolAddress((void**)&attn, g_attn);
    cudaGetSymbolAddress((void**)&proj, g_proj);
    cudaGetSymbolAddress((void**)&x1,   g_x1);
    cudaGetSymbolAddress((void**)&x1r,  g_x1r);
    cudaGetSymbolAddress((void**)&h1,   g_h1);
    cudaGetSymbolAddress((void**)&ff,   g_ff);
    cudaGetSymbolAddress((void**)&Wqr,  g_Wqr);
    cudaGetSymbolAddress((void**)&Wkr,  g_Wkr);
    cudaGetSymbolAddress((void**)&Wvr,  g_Wvr);
    cudaGetSymbolAddress((void**)&Wor,  g_Wor);
    cudaGetSymbolAddress((void**)&W1r,  g_W1r);
    cudaGetSymbolAddress((void**)&W2r,  g_W2r);

    const int SMEM_GEMM = NSTAGE * STAGE_BYTES;   // 98304 bytes
    cudaFuncSetAttribute(tc_gemm_kernel, cudaFuncAttributeMaxDynamicSharedMemorySize, SMEM_GEMM);

    // 0. pre-round weights to tf32
    const int n512 = DIM * DIM / 4, nff = PF * DIM / 4;
    wcvt_kernel<<<(n512 + 255) / 256, 256>>>(Wq, Wqr, n512);
    wcvt_kernel<<<(n512 + 255) / 256, 256>>>(Wk, Wkr, n512);
    wcvt_kernel<<<(n512 + 255) / 256, 256>>>(Wv, Wvr, n512);
    wcvt_kernel<<<(n512 + 255) / 256, 256>>>(Wo, Wor, n512);
    wcvt_kernel<<<(nff + 255) / 256, 256>>>(W1, W1r, nff);
    wcvt_kernel<<<(nff + 255) / 256, 256>>>(W2, W2r, nff);

    // 1. stack streams (exact + rounded)
    pack_kernel<<<(HALF_M * DIM / 4 + 255) / 256, 256>>>(question, query);

    // 2. QKV projections
    dim3 g512(DIM / 128, MTOT / 128);
    tc_gemm_kernel<<<g512, 256, SMEM_GEMM>>>(Xr, Wqr, bq, Q, DIM, DIM, 0, 0);
    tc_gemm_kernel<<<g512, 256, SMEM_GEMM>>>(Xr, Wkr, bk, K, DIM, DIM, 0, 0);
    tc_gemm_kernel<<<g512, 256, SMEM_GEMM>>>(Xr, Wvr, bv, V, DIM, DIM, 0, 0);

    // 3. shared linear-attention state
    s_kernel<<<NB * NH, 256>>>();

    // 4. attn = Q @ S (rounded output)
    qs_kernel<<<dim3(MTOT / 64, NH), 256>>>();

    // 5. output projection
    tc_gemm_kernel<<<g512, 256, SMEM_GEMM>>>(attn, Wor, bo, proj, DIM, DIM, 0, 0);

    // 6. LN1: x1 exact + x1r rounded
    ln_kernel<<<MTOT, 128>>>(X, proj, ln_g, ln_b, x1, x1r, 0);

    // 7. FF1 (ReLU fused, rounded output)
    tc_gemm_kernel<<<dim3(PF / 128, MTOT / 128), 256, SMEM_GEMM>>>(x1r, W1r, b1, h1, DIM, PF, 1, 1);

    // 8. FF2
    tc_gemm_kernel<<<dim3(DIM / 128, MTOT / 128), 256, SMEM_GEMM>>>(h1, W2r, b2, ff, PF, DIM, 0, 0);

    // 9. LN2 + residual + concat
    ln_kernel<<<MTOT, 128>>>(x1, ff, ln_g, ln_b, out, nullptr, 1);
}

// round 7
// speedup vs baseline: 1.2068x; 1.2068x over previous
#include <cuda_runtime.h>
#include <cstdint>

// Problem constants
#define MTOT 16384      // 2 streams * B(4) * L(2048)
#define HALF_M 8192
#define DIM 512
#define PF 2048
#define QKVN 1536
#define NB 4
#define NH 8
#define DH 64
#define LN_EPS 1e-5f
#define NSLICE 8

// ---------------- scratch (static device globals; no allocation) -------------
__device__ float g_X    [MTOT * DIM];    // exact stacked input (residual)
__device__ float g_Xr   [MTOT * DIM];    // tf32-rounded stacked input
__device__ float g_QKV  [MTOT * QKVN];   // fused QKV output [Q|K|V] per row
__device__ float g_attn [MTOT * DIM];    // rounded at qs output
__device__ float g_proj [MTOT * DIM];
__device__ float g_x1   [MTOT * DIM];    // exact (LN2 residual)
__device__ float g_x1r  [MTOT * DIM];    // rounded (FF1 operand)
__device__ float g_h1   [MTOT * PF];     // rounded at FF1 epilogue
__device__ float g_ff   [MTOT * DIM];
__device__ float g_S    [NB * NH * DH * DH];
__device__ float g_Spart[NSLICE * NB * NH * DH * DH];
// packed / rounded weights + bias
__device__ float g_Wqkvr[QKVN * DIM];
__device__ float g_bqkv [QKVN];
__device__ float g_Wor  [DIM * DIM];
__device__ float g_W1r  [PF * DIM];
__device__ float g_W2r  [DIM * PF];

// ---------------- helpers ----------------------------------------------------
__device__ __forceinline__ uint32_t f2tf(float f) {
    uint32_t r;
    asm("cvt.rna.tf32.f32 %0, %1;" : "=r"(r) : "f"(f));
    return r;
}
__device__ __forceinline__ float roundtf(float f) { return __uint_as_float(f2tf(f)); }
__device__ __forceinline__ float4 round4(float4 v) {
    return make_float4(roundtf(v.x), roundtf(v.y), roundtf(v.z), roundtf(v.w));
}
__device__ __forceinline__ uint32_t smem_u32(const void* p) {
    uint32_t a;
    asm("{ .reg .u64 t; cvta.to.shared.u64 t, %1; cvt.u32.u64 %0, t; }" : "=r"(a) : "l"(p));
    return a;
}
__device__ __forceinline__ void mma_tf32(float& c0, float& c1, float& c2, float& c3,
                                         uint32_t a0, uint32_t a1, uint32_t a2, uint32_t a3,
                                         uint32_t b0, uint32_t b1)
{
    asm volatile(
        "mma.sync.aligned.m16n8k8.row.col.f32.tf32.tf32.f32 "
        "{%0,%1,%2,%3}, {%4,%5,%6,%7}, {%8,%9}, {%0,%1,%2,%3};"
        : "+f"(c0), "+f"(c1), "+f"(c2), "+f"(c3)
        : "r"(a0), "r"(a1), "r"(a2), "r"(a3), "r"(b0), "r"(b1));
}
__device__ __forceinline__ void ldsm4(uint32_t& r0, uint32_t& r1, uint32_t& r2, uint32_t& r3,
                                      uint32_t addr)
{
    asm volatile("ldmatrix.sync.aligned.m8n8.x4.shared.b16 {%0,%1,%2,%3}, [%4];"
                 : "=r"(r0), "=r"(r1), "=r"(r2), "=r"(r3) : "r"(addr));
}
__device__ __forceinline__ void cp16(uint32_t saddr, const float* g) {
    asm volatile("cp.async.cg.shared.global [%0], [%1], 16;" :: "r"(saddr), "l"(g) : "memory");
}

// ---------------- prep: pack+round all weights / biases (one launch) ----------
// float4 regions: [0,196608) QKV  [196608,262144) Wo  [262144,524288) W1
//                 [524288,786432) W2  [786432,786816) bias qkv
__global__ void prep_kernel(const float* __restrict__ Wq, const float* __restrict__ Wk,
                            const float* __restrict__ Wv, const float* __restrict__ Wo,
                            const float* __restrict__ W1, const float* __restrict__ W2,
                            const float* __restrict__ bq, const float* __restrict__ bk,
                            const float* __restrict__ bv)
{
    int i = blockIdx.x * blockDim.x + threadIdx.x;
    if (i < 196608) {
        int which = i >> 16, off = i & 65535;
        const float4* src = reinterpret_cast<const float4*>(which == 0 ? Wq : (which == 1 ? Wk : Wv));
        reinterpret_cast<float4*>(g_Wqkvr)[i] = round4(src[off]);
    } else if (i < 262144) {
        reinterpret_cast<float4*>(g_Wor)[i - 196608] =
            round4(reinterpret_cast<const float4*>(Wo)[i - 196608]);
    } else if (i < 524288) {
        reinterpret_cast<float4*>(g_W1r)[i - 262144] =
            round4(reinterpret_cast<const float4*>(W1)[i - 262144]);
    } else if (i < 786432) {
        reinterpret_cast<float4*>(g_W2r)[i - 524288] =
            round4(reinterpret_cast<const float4*>(W2)[i - 524288]);
    } else if (i < 786816) {
        int j = i - 786432;  // 0..383
        const float4* src = reinterpret_cast<const float4*>(j < 128 ? bq : (j < 256 ? bk : bv));
        reinterpret_cast<float4*>(g_bqkv)[j] = src[j & 127];
    }
}

// ---------------- pack: exact + rounded ---------------------------------------
__global__ void pack_kernel(const float* __restrict__ a, const float* __restrict__ b) {
    int i = blockIdx.x * blockDim.x + threadIdx.x;
    const int n4 = HALF_M * DIM / 4;
    float4* X  = reinterpret_cast<float4*>(g_X);
    float4* Xr = reinterpret_cast<float4*>(g_Xr);
    if (i < n4) {
        float4 va = reinterpret_cast<const float4*>(a)[i];
        float4 vb = reinterpret_cast<const float4*>(b)[i];
        X[i] = va;            X[i + n4] = vb;
        Xr[i] = round4(va);   Xr[i + n4] = round4(vb);
    }
}

// ============ tf32 mma.sync GEMM (cp.async 3-stage, swizzled smem) ============
#define NSTAGE 3
#define STAGE_BYTES 32768

__global__ void __launch_bounds__(256)
tc_gemm_kernel(const float* __restrict__ A, const float* __restrict__ W,
               const float* __restrict__ bias, float* __restrict__ C,
               int K, int N, int relu, int rnd)
{
    extern __shared__ float smem[];

    const int tid  = threadIdx.x;
    const int wid  = tid >> 5;
    const int lane = tid & 31;
    const int g    = lane >> 2;
    const int tg   = lane & 3;
    const int wm   = wid >> 2;
    const int wn   = wid & 3;
    const int bm = blockIdx.y, bn = blockIdx.x;

    const float* Ag = A + (size_t)bm * 128 * K;
    const float* Wg = W + (size_t)bn * 128 * K;

    const uint32_t sb = smem_u32(smem);

    uint32_t stOff[4];
    size_t   gOff[4];
#pragma unroll
    for (int i = 0; i < 4; i++) {
        int idx = i * 256 + tid;
        int row = idx >> 3, seg = idx & 7;
        stOff[i] = (uint32_t)(row * 128 + ((seg ^ (row & 7)) << 4));
        gOff[i]  = (size_t)row * K + seg * 4;
    }

    const int rowA = ((lane >> 3) & 1) * 8 + (lane & 7);
    const int cA   = (lane >> 4);
    const int rowB = ((lane >> 4) & 1) * 8 + (lane & 7);
    const int cB   = ((lane >> 3) & 1);
    const uint32_t mask = (uint32_t)(lane & 7);

    uint32_t aRowOff[4], bRowOff[2];
#pragma unroll
    for (int mi = 0; mi < 4; mi++)
        aRowOff[mi] = (uint32_t)((wm * 64 + mi * 16 + rowA) * 128);
#pragma unroll
    for (int n2 = 0; n2 < 2; n2++)
        bRowOff[n2] = (uint32_t)(16384 + (wn * 32 + n2 * 16 + rowB) * 128);

    float acc[4][4][4];
#pragma unroll
    for (int mi = 0; mi < 4; mi++)
#pragma unroll
        for (int ni = 0; ni < 4; ni++)
#pragma unroll
            for (int r = 0; r < 4; r++) acc[mi][ni][r] = 0.f;

    const int NC = K >> 5;

#pragma unroll
    for (int p = 0; p < 2; p++) {
        uint32_t st = sb + p * STAGE_BYTES;
        size_t go = (size_t)p * 32;
#pragma unroll
        for (int i = 0; i < 4; i++) {
            cp16(st + stOff[i],         Ag + gOff[i] + go);
            cp16(st + 16384 + stOff[i], Wg + gOff[i] + go);
        }
        asm volatile("cp.async.commit_group;" ::: "memory");
    }

    for (int c = 0; c < NC; ++c) {
        asm volatile("cp.async.wait_group 1;" ::: "memory");
        __syncthreads();

        if (c + 2 < NC) {
            int s2 = (c + 2) % NSTAGE;
            uint32_t st = sb + s2 * STAGE_BYTES;
            size_t go = (size_t)(c + 2) * 32;
#pragma unroll
            for (int i = 0; i < 4; i++) {
                cp16(st + stOff[i],         Ag + gOff[i] + go);
                cp16(st + 16384 + stOff[i], Wg + gOff[i] + go);
            }
        }
        asm volatile("cp.async.commit_group;" ::: "memory");

        const uint32_t base = sb + (c % NSTAGE) * STAGE_BYTES;
#pragma unroll
        for (int ks = 0; ks < 4; ks++) {
            uint32_t a[4][4];
#pragma unroll
            for (int mi = 0; mi < 4; mi++)
                ldsm4(a[mi][0], a[mi][1], a[mi][2], a[mi][3],
                      base + aRowOff[mi] + ((((uint32_t)(ks * 2 + cA)) ^ mask) << 4));
            uint32_t b[2][4];
#pragma unroll
            for (int n2 = 0; n2 < 2; n2++)
                ldsm4(b[n2][0], b[n2][1], b[n2][2], b[n2][3],
                      base + bRowOff[n2] + ((((uint32_t)(ks * 2 + cB)) ^ mask) << 4));
#pragma unroll
            for (int mi = 0; mi < 4; mi++)
#pragma unroll
                for (int ni = 0; ni < 4; ni++) {
                    const uint32_t b0 = (ni & 1) ? b[ni >> 1][2] : b[ni >> 1][0];
                    const uint32_t b1 = (ni & 1) ? b[ni >> 1][3] : b[ni >> 1][1];
                    mma_tf32(acc[mi][ni][0], acc[mi][ni][1], acc[mi][ni][2], acc[mi][ni][3],
                             a[mi][0], a[mi][1], a[mi][2], a[mi][3], b0, b1);
                }
        }
    }

    const float2* bias2 = reinterpret_cast<const float2*>(bias);
#pragma unroll
    for (int mi = 0; mi < 4; mi++) {
        int r0 = bm * 128 + wm * 64 + mi * 16 + g;
#pragma unroll
        for (int ni = 0; ni < 4; ni++) {
            int col = bn * 128 + wn * 32 + ni * 8 + 2 * tg;
            float2 bv = __ldg(&bias2[col >> 1]);
            float2 o0, o1;
            o0.x = acc[mi][ni][0] + bv.x;
            o0.y = acc[mi][ni][1] + bv.y;
            o1.x = acc[mi][ni][2] + bv.x;
            o1.y = acc[mi][ni][3] + bv.y;
            if (relu) {
                o0.x = fmaxf(o0.x, 0.f); o0.y = fmaxf(o0.y, 0.f);
                o1.x = fmaxf(o1.x, 0.f); o1.y = fmaxf(o1.y, 0.f);
            }
            if (rnd) {
                o0.x = roundtf(o0.x); o0.y = roundtf(o0.y);
                o1.x = roundtf(o1.x); o1.y = roundtf(o1.y);
            }
            *reinterpret_cast<float2*>(C + (size_t)r0 * N + col) = o0;
            *reinterpret_cast<float2*>(C + (size_t)(r0 + 8) * N + col) = o1;
        }
    }
}

// ---------------- S partial: slice j of rows, S[b,h] += K^T V -----------------
// grid: (32 bh, 8 slices). Row range per (b): both streams' 2048-blocks, 4096 rows.
__global__ void __launch_bounds__(256)
s_partial_kernel()
{
    const int bh = blockIdx.x;
    const int j  = blockIdx.y;
    const int b = bh >> 3;
    const int h = bh & 7;
    __shared__ float Ks[32][64];
    __shared__ float Vs[32][64];

    const int tid = threadIdx.x;
    const int te = tid & 15;
    const int td = tid >> 4;

    float acc[4][4];
#pragma unroll
    for (int i = 0; i < 4; i++)
#pragma unroll
        for (int k = 0; k < 4; k++) acc[i][k] = 0.f;

    const size_t koff = 512 + (size_t)h * DH;
    const size_t voff = 1024 + (size_t)h * DH;

    for (int t0 = 0; t0 < 512; t0 += 32) {
        const int g0 = j * 512 + t0;              // 0..4095
        const int s = g0 >> 11;                    // stream
        const int baseRow = (s * 4 + b) * 2048 + (g0 & 2047);
#pragma unroll
        for (int i = 0; i < 2; i++) {
            int idx = tid + i * 256;
            int l = idx >> 4;
            int ec = (idx & 15) * 4;
            size_t roff = (size_t)(baseRow + l) * QKVN;
            *reinterpret_cast<float4*>(&Ks[l][ec]) =
                *reinterpret_cast<const float4*>(&g_QKV[roff + koff + ec]);
            *reinterpret_cast<float4*>(&Vs[l][ec]) =
                *reinterpret_cast<const float4*>(&g_QKV[roff + voff + ec]);
        }
        __syncthreads();
#pragma unroll 8
        for (int l = 0; l < 32; l++) {
            float kr[4], vr[4];
            *reinterpret_cast<float4*>(kr) = *reinterpret_cast<const float4*>(&Ks[l][te * 4]);
            *reinterpret_cast<float4*>(vr) = *reinterpret_cast<const float4*>(&Vs[l][td * 4]);
#pragma unroll
            for (int i = 0; i < 4; i++)
#pragma unroll
                for (int k = 0; k < 4; k++)
                    acc[i][k] += kr[i] * vr[k];
        }
        __syncthreads();
    }

    float* Sp = &g_Spart[((size_t)j * 32 + bh) * (DH * DH)];
#pragma unroll
    for (int i = 0; i < 4; i++) {
        int e = te * 4 + i;
        *reinterpret_cast<float4*>(&Sp[e * DH + td * 4]) =
            make_float4(acc[i][0], acc[i][1], acc[i][2], acc[i][3]);
    }
}

// ---------------- S reduce: sum 8 partials -------------------------------------
__global__ void __launch_bounds__(256)
s_reduce_kernel()
{
    const int bh = blockIdx.x;
    const int tid = threadIdx.x;
#pragma unroll
    for (int i = 0; i < 4; i++) {
        int idx4 = tid + i * 256;   // float4 index 0..1023
        float4 acc = make_float4(0.f, 0.f, 0.f, 0.f);
#pragma unroll
        for (int j = 0; j < NSLICE; j++) {
            float4 v = reinterpret_cast<const float4*>(
                &g_Spart[((size_t)j * 32 + bh) * (DH * DH)])[idx4];
            acc.x += v.x; acc.y += v.y; acc.z += v.z; acc.w += v.w;
        }
        reinterpret_cast<float4*>(&g_S[(size_t)bh * (DH * DH)])[idx4] = acc;
    }
}

// ---------------- Q @ S -> attn (rounded output) ------------------------------
__global__ void __launch_bounds__(256)
qs_kernel()
{
    const int h = blockIdx.y;
    const int r0 = blockIdx.x * 64;
    const int b = (r0 >> 11) & 3;

    __shared__ float Ss[64][64];
    __shared__ float Qs[64][72];

    const int tid = threadIdx.x;

    const float* Sp = &g_S[(b * 8 + h) * DH * DH];
#pragma unroll
    for (int i = 0; i < 4; i++) {
        int idx = tid + i * 256;
        reinterpret_cast<float4*>(Ss)[idx] = reinterpret_cast<const float4*>(Sp)[idx];
    }
#pragma unroll
    for (int i = 0; i < 4; i++) {
        int idx = tid + i * 256;
        int l = idx >> 4;
        int ec = (idx & 15) * 4;
        *reinterpret_cast<float4*>(&Qs[l][ec]) =
            *reinterpret_cast<const float4*>(&g_QKV[(size_t)(r0 + l) * QKVN + h * DH + ec]);
    }
    __syncthreads();

    const int rl = tid >> 2;
    const int d0 = (tid & 3) * 16;

    float acc[16];
#pragma unroll
    for (int k = 0; k < 16; k++) acc[k] = 0.f;

#pragma unroll 4
    for (int e = 0; e < 64; e++) {
        float q = Qs[rl][e];
#pragma unroll
        for (int k = 0; k < 16; k += 4) {
            float4 sv = *reinterpret_cast<const float4*>(&Ss[e][d0 + k]);
            acc[k + 0] += q * sv.x;
            acc[k + 1] += q * sv.y;
            acc[k + 2] += q * sv.z;
            acc[k + 3] += q * sv.w;
        }
    }

    size_t base = (size_t)(r0 + rl) * DIM + h * DH + d0;
#pragma unroll
    for (int k = 0; k < 16; k += 4) {
        *reinterpret_cast<float4*>(&g_attn[base + k]) =
            make_float4(roundtf(acc[k]), roundtf(acc[k + 1]),
                        roundtf(acc[k + 2]), roundtf(acc[k + 3]));
    }
}

// ---------------- fused residual + LayerNorm ----------------------------------
__global__ void __launch_bounds__(128)
ln_kernel(const float* __restrict__ A, const float* __restrict__ R,
          const float* __restrict__ gamma, const float* __restrict__ beta,
          float* __restrict__ out, float* __restrict__ out2, int concat)
{
    const int row = blockIdx.x;
    const int tid = threadIdx.x;
    const int c = tid * 4;
    const size_t off = (size_t)row * DIM + c;

    float4 a = *reinterpret_cast<const float4*>(A + off);
    float4 r = *reinterpret_cast<const float4*>(R + off);
    float v0 = a.x + r.x, v1 = a.y + r.y, v2 = a.z + r.z, v3 = a.w + r.w;

    float s = v0 + v1 + v2 + v3;
    float q = v0 * v0 + v1 * v1 + v2 * v2 + v3 * v3;
#pragma unroll
    for (int o = 16; o > 0; o >>= 1) {
        s += __shfl_xor_sync(0xffffffffu, s, o);
        q += __shfl_xor_sync(0xffffffffu, q, o);
    }
    __shared__ float ss[4], sq[4];
    if ((tid & 31) == 0) { ss[tid >> 5] = s; sq[tid >> 5] = q; }
    __syncthreads();
    s = ss[0] + ss[1] + ss[2] + ss[3];
    q = sq[0] + sq[1] + sq[2] + sq[3];

    const float mean = s * (1.f / DIM);
    const float var = q * (1.f / DIM) - mean * mean;
    const float rstd = rsqrtf(var + LN_EPS);

    float4 gv = *reinterpret_cast<const float4*>(gamma + c);
    float4 bv = *reinterpret_cast<const float4*>(beta + c);
    float4 o;
    o.x = (v0 - mean) * rstd * gv.x + bv.x;
    o.y = (v1 - mean) * rstd * gv.y + bv.y;
    o.z = (v2 - mean) * rstd * gv.z + bv.z;
    o.w = (v3 - mean) * rstd * gv.w + bv.w;

    if (!concat) {
        *reinterpret_cast<float4*>(out + off) = o;
        if (out2) *reinterpret_cast<float4*>(out2 + off) = round4(o);
    } else {
        int sdx = row >> 13;
        int rem = row & 8191;
        *reinterpret_cast<float4*>(out + (size_t)rem * 1024 + sdx * 512 + c) = o;
    }
}

// ---------------- launch ------------------------------------------------------
extern "C" void kernel_launch(void* const* d_in, const int* in_sizes, int n_in,
                              void* d_out, int out_size)
{
    (void)in_sizes; (void)n_in; (void)out_size;
    const float* question = (const float*)d_in[0];
    const float* query    = (const float*)d_in[1];
    const float* Wq = (const float*)d_in[2];
    const float* bq = (const float*)d_in[3];
    const float* Wk = (const float*)d_in[4];
    const float* bk = (const float*)d_in[5];
    const float* Wv = (const float*)d_in[6];
    const float* bv = (const float*)d_in[7];
    const float* Wo = (const float*)d_in[8];
    const float* bo = (const float*)d_in[9];
    const float* ln_g = (const float*)d_in[10];
    const float* ln_b = (const float*)d_in[11];
    const float* W1 = (const float*)d_in[12];
    const float* b1 = (const float*)d_in[13];
    const float* W2 = (const float*)d_in[14];
    const float* b2 = (const float*)d_in[15];
    float* out = (float*)d_out;

    float *X, *Xr, *QKV, *attn, *proj, *x1, *x1r, *h1, *ff;
    float *Wqkvr, *bqkv, *Wor, *W1r, *W2r;
    cudaGetSymbolAddress((void**)&X,     g_X);
    cudaGetSymbolAddress((void**)&Xr,    g_Xr);
    cudaGetSymbolAddress((void**)&QKV,   g_QKV);
    cudaGetSymbolAddress((void**)&attn,  g_attn);
    cudaGetSymbolAddress((void**)&proj,  g_proj);
    cudaGetSymbolAddress((void**)&x1,    g_x1);
    cudaGetSymbolAddress((void**)&x1r,   g_x1r);
    cudaGetSymbolAddress((void**)&h1,    g_h1);
    cudaGetSymbolAddress((void**)&ff,    g_ff);
    cudaGetSymbolAddress((void**)&Wqkvr, g_Wqkvr);
    cudaGetSymbolAddress((void**)&bqkv,  g_bqkv);
    cudaGetSymbolAddress((void**)&Wor,   g_Wor);
    cudaGetSymbolAddress((void**)&W1r,   g_W1r);
    cudaGetSymbolAddress((void**)&W2r,   g_W2r);

    const int SMEM_GEMM = NSTAGE * STAGE_BYTES;   // 98304 bytes
    cudaFuncSetAttribute(tc_gemm_kernel, cudaFuncAttributeMaxDynamicSharedMemorySize, SMEM_GEMM);

    // 0. pack + round all weights/biases (one launch)
    prep_kernel<<<(786816 + 255) / 256, 256>>>(Wq, Wk, Wv, Wo, W1, W2, bq, bk, bv);

    // 1. stack streams (exact + rounded)
    pack_kernel<<<(HALF_M * DIM / 4 + 255) / 256, 256>>>(question, query);

    // 2. fused QKV projection: [16384 x 1536]
    tc_gemm_kernel<<<dim3(QKVN / 128, MTOT / 128), 256, SMEM_GEMM>>>(
        Xr, Wqkvr, bqkv, QKV, DIM, QKVN, 0, 0);

    // 3. shared linear-attention state (split + reduce)
    s_partial_kernel<<<dim3(NB * NH, NSLICE), 256>>>();
    s_reduce_kernel<<<NB * NH, 256>>>();

    // 4. attn = Q @ S (rounded output)
    qs_kernel<<<dim3(MTOT / 64, NH), 256>>>();

    // 5. output projection
    tc_gemm_kernel<<<dim3(DIM / 128, MTOT / 128), 256, SMEM_GEMM>>>(
        attn, Wor, bo, proj, DIM, DIM, 0, 0);

    // 6. LN1: x1 exact + x1r rounded
    ln_kernel<<<MTOT, 128>>>(X, proj, ln_g, ln_b, x1, x1r, 0);

    // 7. FF1 (ReLU fused, rounded output)
    tc_gemm_kernel<<<dim3(PF / 128, MTOT / 128), 256, SMEM_GEMM>>>(
        x1r, W1r, b1, h1, DIM, PF, 1, 1);

    // 8. FF2
    tc_gemm_kernel<<<dim3(DIM / 128, MTOT / 128), 256, SMEM_GEMM>>>(
        h1, W2r, b2, ff, PF, DIM, 0, 0);

    // 9. LN2 + residual + concat
    ln_kernel<<<MTOT, 128>>>(x1, ff, ln_g, ln_b, out, nullptr, 1);
}

// round 8
// speedup vs baseline: 1.6198x; 1.3422x over previous
#include <cuda_runtime.h>
#include <cuda_fp16.h>
#include <cstdint>

// Problem constants
#define MTOT 16384      // 2 streams * B(4) * L(2048)
#define HALF_M 8192
#define DIM 512
#define PF 2048
#define QKVN 1536
#define NB 4
#define NH 8
#define DH 64
#define LN_EPS 1e-5f
#define NSLICE 8

// ---------------- scratch (static device globals; no allocation) -------------
__device__ float  g_X    [MTOT * DIM];    // exact stacked input (residual)
__device__ __half g_Xh   [MTOT * DIM];    // fp16 stacked input (GEMM operand)
__device__ float  g_QKV  [MTOT * QKVN];   // fused QKV output [Q|K|V] per row
__device__ __half g_attnh[MTOT * DIM];    // fp16 attn (Wo operand)
__device__ float  g_proj [MTOT * DIM];
__device__ float  g_x1   [MTOT * DIM];    // exact (LN2 residual)
__device__ __half g_x1h  [MTOT * DIM];    // fp16 (FF1 operand)
__device__ __half g_h1h  [MTOT * PF];     // fp16 FF intermediate
__device__ float  g_ff   [MTOT * DIM];
__device__ float  g_S    [NB * NH * DH * DH];
__device__ float  g_Spart[NSLICE * NB * NH * DH * DH];
// packed fp16 weights + fp32 bias
__device__ __half g_Wqkvh[QKVN * DIM];
__device__ float  g_bqkv [QKVN];
__device__ __half g_Woh  [DIM * DIM];
__device__ __half g_W1h  [PF * DIM];
__device__ __half g_W2h  [DIM * PF];

// ---------------- helpers ----------------------------------------------------
__device__ __forceinline__ uint32_t smem_u32(const void* p) {
    uint32_t a;
    asm("{ .reg .u64 t; cvta.to.shared.u64 t, %1; cvt.u32.u64 %0, t; }" : "=r"(a) : "l"(p));
    return a;
}
__device__ __forceinline__ void mma_f16(float& c0, float& c1, float& c2, float& c3,
                                        uint32_t a0, uint32_t a1, uint32_t a2, uint32_t a3,
                                        uint32_t b0, uint32_t b1)
{
    asm volatile(
        "mma.sync.aligned.m16n8k16.row.col.f32.f16.f16.f32 "
        "{%0,%1,%2,%3}, {%4,%5,%6,%7}, {%8,%9}, {%0,%1,%2,%3};"
        : "+f"(c0), "+f"(c1), "+f"(c2), "+f"(c3)
        : "r"(a0), "r"(a1), "r"(a2), "r"(a3), "r"(b0), "r"(b1));
}
__device__ __forceinline__ void ldsm4(uint32_t& r0, uint32_t& r1, uint32_t& r2, uint32_t& r3,
                                      uint32_t addr)
{
    asm volatile("ldmatrix.sync.aligned.m8n8.x4.shared.b16 {%0,%1,%2,%3}, [%4];"
                 : "=r"(r0), "=r"(r1), "=r"(r2), "=r"(r3) : "r"(addr));
}
__device__ __forceinline__ void cp16(uint32_t saddr, const void* g) {
    asm volatile("cp.async.cg.shared.global [%0], [%1], 16;" :: "r"(saddr), "l"(g) : "memory");
}
__device__ __forceinline__ void h4store(__half* dst, float4 v) {
    __half2* d = reinterpret_cast<__half2*>(dst);
    d[0] = __floats2half2_rn(v.x, v.y);
    d[1] = __floats2half2_rn(v.z, v.w);
}

// ---------------- prep: pack+convert all weights / biases (one launch) --------
// float4-index regions: [0,196608) QKV W  [196608,262144) Wo  [262144,524288) W1
//                       [524288,786432) W2  [786432,786816) bias qkv
__global__ void prep_kernel(const float* __restrict__ Wq, const float* __restrict__ Wk,
                            const float* __restrict__ Wv, const float* __restrict__ Wo,
                            const float* __restrict__ W1, const float* __restrict__ W2,
                            const float* __restrict__ bq, const float* __restrict__ bk,
                            const float* __restrict__ bv)
{
    int i = blockIdx.x * blockDim.x + threadIdx.x;
    if (i < 196608) {
        int which = i >> 16, off = i & 65535;
        const float4* src = reinterpret_cast<const float4*>(which == 0 ? Wq : (which == 1 ? Wk : Wv));
        h4store(&g_Wqkvh[(size_t)i * 4], src[off]);
    } else if (i < 262144) {
        int j = i - 196608;
        h4store(&g_Woh[(size_t)j * 4], reinterpret_cast<const float4*>(Wo)[j]);
    } else if (i < 524288) {
        int j = i - 262144;
        h4store(&g_W1h[(size_t)j * 4], reinterpret_cast<const float4*>(W1)[j]);
    } else if (i < 786432) {
        int j = i - 524288;
        h4store(&g_W2h[(size_t)j * 4], reinterpret_cast<const float4*>(W2)[j]);
    } else if (i < 786816) {
        int j = i - 786432;  // 0..383
        const float4* src = reinterpret_cast<const float4*>(j < 128 ? bq : (j < 256 ? bk : bv));
        reinterpret_cast<float4*>(g_bqkv)[j] = src[j & 127];
    }
}

// ---------------- pack: exact fp32 + fp16 --------------------------------------
__global__ void pack_kernel(const float* __restrict__ a, const float* __restrict__ b) {
    int i = blockIdx.x * blockDim.x + threadIdx.x;
    const int n4 = HALF_M * DIM / 4;
    float4* X = reinterpret_cast<float4*>(g_X);
    if (i < n4) {
        float4 va = reinterpret_cast<const float4*>(a)[i];
        float4 vb = reinterpret_cast<const float4*>(b)[i];
        X[i] = va;  X[i + n4] = vb;
        h4store(&g_Xh[(size_t)i * 4], va);
        h4store(&g_Xh[(size_t)(i + n4) * 4], vb);
    }
}

// ============ fp16 mma.sync GEMM (cp.async 3-stage, padded-row smem) ==========
// C[M,N] = A[M,K] @ W[N,K]^T + bias (fp32 accum). A,W are fp16, K mult of 32.
// 128x128 CTA tile, BK=32, 256 threads (8 warps 2x4), warp tile 64x32.
// Stage: A rows 128 x 80B (64B data + 16B pad), then B same. Pad makes the 8
// row-addresses of every ldmatrix hit 8 distinct 16B bank-groups.
#define ROWB 80
#define OPER_BYTES (128 * ROWB)      // 10240
#define STAGE_BYTES (2 * OPER_BYTES) // 20480
#define NSTAGE 3

__global__ void __launch_bounds__(256)
hgemm_kernel(const __half* __restrict__ A, const __half* __restrict__ W,
             const float* __restrict__ bias, void* __restrict__ Cv,
             int K, int N, int relu, int outHalf)
{
    extern __shared__ char smem[];

    const int tid  = threadIdx.x;
    const int wid  = tid >> 5;
    const int lane = tid & 31;
    const int g    = lane >> 2;
    const int tg   = lane & 3;
    const int wm   = wid >> 2;
    const int wn   = wid & 3;
    const int bm = blockIdx.y, bn = blockIdx.x;

    const __half* Ag = A + (size_t)bm * 128 * K;
    const __half* Wg = W + (size_t)bn * 128 * K;

    const uint32_t sb = smem_u32(smem);

    // cp.async mapping: 2 iters per operand; idx=i*256+tid; row=idx>>2, seg=idx&3
    uint32_t stOff[2];
    size_t   gOff[2];
#pragma unroll
    for (int i = 0; i < 2; i++) {
        int idx = i * 256 + tid;
        int row = idx >> 2, seg = idx & 3;
        stOff[i] = (uint32_t)(row * ROWB + seg * 16);
        gOff[i]  = (size_t)row * K + seg * 8;       // half elements
    }

    // ldmatrix lane addressing (same mapping as proven tf32 kernel)
    const int rowA = ((lane >> 3) & 1) * 8 + (lane & 7);
    const int cA   = (lane >> 4);            // 16B k-chunk select within slice
    const int rowB = ((lane >> 4) & 1) * 8 + (lane & 7);
    const int cB   = ((lane >> 3) & 1);

    uint32_t aRowOff[4], bRowOff[2];
#pragma unroll
    for (int mi = 0; mi < 4; mi++)
        aRowOff[mi] = (uint32_t)((wm * 64 + mi * 16 + rowA) * ROWB);
#pragma unroll
    for (int n2 = 0; n2 < 2; n2++)
        bRowOff[n2] = (uint32_t)(OPER_BYTES + (wn * 32 + n2 * 16 + rowB) * ROWB);

    float acc[4][4][4];
#pragma unroll
    for (int mi = 0; mi < 4; mi++)
#pragma unroll
        for (int ni = 0; ni < 4; ni++)
#pragma unroll
            for (int r = 0; r < 4; r++) acc[mi][ni][r] = 0.f;

    const int NC = K >> 5;

    // prologue: stages 0,1
#pragma unroll
    for (int p = 0; p < 2; p++) {
        uint32_t st = sb + p * STAGE_BYTES;
        size_t go = (size_t)p * 32;
#pragma unroll
        for (int i = 0; i < 2; i++) {
            cp16(st + stOff[i],              Ag + gOff[i] + go);
            cp16(st + OPER_BYTES + stOff[i], Wg + gOff[i] + go);
        }
        asm volatile("cp.async.commit_group;" ::: "memory");
    }

    for (int c = 0; c < NC; ++c) {
        asm volatile("cp.async.wait_group 1;" ::: "memory");
        __syncthreads();

        if (c + 2 < NC) {
            int s2 = (c + 2) % NSTAGE;
            uint32_t st = sb + s2 * STAGE_BYTES;
            size_t go = (size_t)(c + 2) * 32;
#pragma unroll
            for (int i = 0; i < 2; i++) {
                cp16(st + stOff[i],              Ag + gOff[i] + go);
                cp16(st + OPER_BYTES + stOff[i], Wg + gOff[i] + go);
            }
        }
        asm volatile("cp.async.commit_group;" ::: "memory");

        const uint32_t base = sb + (c % NSTAGE) * STAGE_BYTES;
        // 2 k-slices of 16
#pragma unroll
        for (int ks = 0; ks < 2; ks++) {
            uint32_t a[4][4];
#pragma unroll
            for (int mi = 0; mi < 4; mi++)
                ldsm4(a[mi][0], a[mi][1], a[mi][2], a[mi][3],
                      base + aRowOff[mi] + (uint32_t)((ks * 2 + cA) * 16));
            uint32_t b[2][4];
#pragma unroll
            for (int n2 = 0; n2 < 2; n2++)
                ldsm4(b[n2][0], b[n2][1], b[n2][2], b[n2][3],
                      base + bRowOff[n2] + (uint32_t)((ks * 2 + cB) * 16));
#pragma unroll
            for (int mi = 0; mi < 4; mi++)
#pragma unroll
                for (int ni = 0; ni < 4; ni++) {
                    const uint32_t b0 = (ni & 1) ? b[ni >> 1][2] : b[ni >> 1][0];
                    const uint32_t b1 = (ni & 1) ? b[ni >> 1][3] : b[ni >> 1][1];
                    mma_f16(acc[mi][ni][0], acc[mi][ni][1], acc[mi][ni][2], acc[mi][ni][3],
                            a[mi][0], a[mi][1], a[mi][2], a[mi][3], b0, b1);
                }
        }
    }

    // ---- epilogue
    const float2* bias2 = reinterpret_cast<const float2*>(bias);
#pragma unroll
    for (int mi = 0; mi < 4; mi++) {
        int r0 = bm * 128 + wm * 64 + mi * 16 + g;
#pragma unroll
        for (int ni = 0; ni < 4; ni++) {
            int col = bn * 128 + wn * 32 + ni * 8 + 2 * tg;
            float2 bv = __ldg(&bias2[col >> 1]);
            float2 o0, o1;
            o0.x = acc[mi][ni][0] + bv.x;
            o0.y = acc[mi][ni][1] + bv.y;
            o1.x = acc[mi][ni][2] + bv.x;
            o1.y = acc[mi][ni][3] + bv.y;
            if (relu) {
                o0.x = fmaxf(o0.x, 0.f); o0.y = fmaxf(o0.y, 0.f);
                o1.x = fmaxf(o1.x, 0.f); o1.y = fmaxf(o1.y, 0.f);
            }
            if (outHalf) {
                __half* C = (__half*)Cv;
                *reinterpret_cast<__half2*>(C + (size_t)r0 * N + col) =
                    __floats2half2_rn(o0.x, o0.y);
                *reinterpret_cast<__half2*>(C + (size_t)(r0 + 8) * N + col) =
                    __floats2half2_rn(o1.x, o1.y);
            } else {
                float* C = (float*)Cv;
                *reinterpret_cast<float2*>(C + (size_t)r0 * N + col) = o0;
                *reinterpret_cast<float2*>(C + (size_t)(r0 + 8) * N + col) = o1;
            }
        }
    }
}

// ---------------- S partial: slice j of rows, S[b,h] += K^T V -----------------
__global__ void __launch_bounds__(256)
s_partial_kernel()
{
    const int bh = blockIdx.x;
    const int j  = blockIdx.y;
    const int b = bh >> 3;
    const int h = bh & 7;
    __shared__ float Ks[32][64];
    __shared__ float Vs[32][64];

    const int tid = threadIdx.x;
    const int te = tid & 15;
    const int td = tid >> 4;

    float acc[4][4];
#pragma unroll
    for (int i = 0; i < 4; i++)
#pragma unroll
        for (int k = 0; k < 4; k++) acc[i][k] = 0.f;

    const size_t koff = 512 + (size_t)h * DH;
    const size_t voff = 1024 + (size_t)h * DH;

    for (int t0 = 0; t0 < 512; t0 += 32) {
        const int g0 = j * 512 + t0;
        const int s = g0 >> 11;
        const int baseRow = (s * 4 + b) * 2048 + (g0 & 2047);
#pragma unroll
        for (int i = 0; i < 2; i++) {
            int idx = tid + i * 256;
            int l = idx >> 4;
            int ec = (idx & 15) * 4;
            size_t roff = (size_t)(baseRow + l) * QKVN;
            *reinterpret_cast<float4*>(&Ks[l][ec]) =
                *reinterpret_cast<const float4*>(&g_QKV[roff + koff + ec]);
            *reinterpret_cast<float4*>(&Vs[l][ec]) =
                *reinterpret_cast<const float4*>(&g_QKV[roff + voff + ec]);
        }
        __syncthreads();
#pragma unroll 8
        for (int l = 0; l < 32; l++) {
            float kr[4], vr[4];
            *reinterpret_cast<float4*>(kr) = *reinterpret_cast<const float4*>(&Ks[l][te * 4]);
            *reinterpret_cast<float4*>(vr) = *reinterpret_cast<const float4*>(&Vs[l][td * 4]);
#pragma unroll
            for (int i = 0; i < 4; i++)
#pragma unroll
                for (int k = 0; k < 4; k++)
                    acc[i][k] += kr[i] * vr[k];
        }
        __syncthreads();
    }

    float* Sp = &g_Spart[((size_t)j * 32 + bh) * (DH * DH)];
#pragma unroll
    for (int i = 0; i < 4; i++) {
        int e = te * 4 + i;
        *reinterpret_cast<float4*>(&Sp[e * DH + td * 4]) =
            make_float4(acc[i][0], acc[i][1], acc[i][2], acc[i][3]);
    }
}

// ---------------- S reduce -----------------------------------------------------
__global__ void __launch_bounds__(256)
s_reduce_kernel()
{
    const int bh = blockIdx.x;
    const int tid = threadIdx.x;
#pragma unroll
    for (int i = 0; i < 4; i++) {
        int idx4 = tid + i * 256;
        float4 acc = make_float4(0.f, 0.f, 0.f, 0.f);
#pragma unroll
        for (int j = 0; j < NSLICE; j++) {
            float4 v = reinterpret_cast<const float4*>(
                &g_Spart[((size_t)j * 32 + bh) * (DH * DH)])[idx4];
            acc.x += v.x; acc.y += v.y; acc.z += v.z; acc.w += v.w;
        }
        reinterpret_cast<float4*>(&g_S[(size_t)bh * (DH * DH)])[idx4] = acc;
    }
}

// ---------------- Q @ S -> attn (fp16 output) ----------------------------------
__global__ void __launch_bounds__(256)
qs_kernel()
{
    const int h = blockIdx.y;
    const int r0 = blockIdx.x * 64;
    const int b = (r0 >> 11) & 3;

    __shared__ float Ss[64][64];
    __shared__ float Qs[64][72];

    const int tid = threadIdx.x;

    const float* Sp = &g_S[(b * 8 + h) * DH * DH];
#pragma unroll
    for (int i = 0; i < 4; i++) {
        int idx = tid + i * 256;
        reinterpret_cast<float4*>(Ss)[idx] = reinterpret_cast<const float4*>(Sp)[idx];
    }
#pragma unroll
    for (int i = 0; i < 4; i++) {
        int idx = tid + i * 256;
        int l = idx >> 4;
        int ec = (idx & 15) * 4;
        *reinterpret_cast<float4*>(&Qs[l][ec]) =
            *reinterpret_cast<const float4*>(&g_QKV[(size_t)(r0 + l) * QKVN + h * DH + ec]);
    }
    __syncthreads();

    const int rl = tid >> 2;
    const int d0 = (tid & 3) * 16;

    float acc[16];
#pragma unroll
    for (int k = 0; k < 16; k++) acc[k] = 0.f;

#pragma unroll 4
    for (int e = 0; e < 64; e++) {
        float q = Qs[rl][e];
#pragma unroll
        for (int k = 0; k < 16; k += 4) {
            float4 sv = *reinterpret_cast<const float4*>(&Ss[e][d0 + k]);
            acc[k + 0] += q * sv.x;
            acc[k + 1] += q * sv.y;
            acc[k + 2] += q * sv.z;
            acc[k + 3] += q * sv.w;
        }
    }

    size_t base = (size_t)(r0 + rl) * DIM + h * DH + d0;
#pragma unroll
    for (int k = 0; k < 16; k += 4)
        h4store(&g_attnh[base + k], make_float4(acc[k], acc[k + 1], acc[k + 2], acc[k + 3]));
}

// ---------------- fused residual + LayerNorm (optional fp16 copy) --------------
__global__ void __launch_bounds__(128)
ln_kernel(const float* __restrict__ A, const float* __restrict__ R,
          const float* __restrict__ gamma, const float* __restrict__ beta,
          float* __restrict__ out, __half* __restrict__ outh, int concat)
{
    const int row = blockIdx.x;
    const int tid = threadIdx.x;
    const int c = tid * 4;
    const size_t off = (size_t)row * DIM + c;

    float4 a = *reinterpret_cast<const float4*>(A + off);
    float4 r = *reinterpret_cast<const float4*>(R + off);
    float v0 = a.x + r.x, v1 = a.y + r.y, v2 = a.z + r.z, v3 = a.w + r.w;

    float s = v0 + v1 + v2 + v3;
    float q = v0 * v0 + v1 * v1 + v2 * v2 + v3 * v3;
#pragma unroll
    for (int o = 16; o > 0; o >>= 1) {
        s += __shfl_xor_sync(0xffffffffu, s, o);
        q += __shfl_xor_sync(0xffffffffu, q, o);
    }
    __shared__ float ss[4], sq[4];
    if ((tid & 31) == 0) { ss[tid >> 5] = s; sq[tid >> 5] = q; }
    __syncthreads();
    s = ss[0] + ss[1] + ss[2] + ss[3];
    q = sq[0] + sq[1] + sq[2] + sq[3];

    const float mean = s * (1.f / DIM);
    const float var = q * (1.f / DIM) - mean * mean;
    const float rstd = rsqrtf(var + LN_EPS);

    float4 gv = *reinterpret_cast<const float4*>(gamma + c);
    float4 bv = *reinterpret_cast<const float4*>(beta + c);
    float4 o;
    o.x = (v0 - mean) * rstd * gv.x + bv.x;
    o.y = (v1 - mean) * rstd * gv.y + bv.y;
    o.z = (v2 - mean) * rstd * gv.z + bv.z;
    o.w = (v3 - mean) * rstd * gv.w + bv.w;

    if (!concat) {
        *reinterpret_cast<float4*>(out + off) = o;
        if (outh) h4store(outh + off, o);
    } else {
        int sdx = row >> 13;
        int rem = row & 8191;
        *reinterpret_cast<float4*>(out + (size_t)rem * 1024 + sdx * 512 + c) = o;
    }
}

// ---------------- launch ------------------------------------------------------
extern "C" void kernel_launch(void* const* d_in, const int* in_sizes, int n_in,
                              void* d_out, int out_size)
{
    (void)in_sizes; (void)n_in; (void)out_size;
    const float* question = (const float*)d_in[0];
    const float* query    = (const float*)d_in[1];
    const float* Wq = (const float*)d_in[2];
    const float* bq = (const float*)d_in[3];
    const float* Wk = (const float*)d_in[4];
    const float* bk = (const float*)d_in[5];
    const float* Wv = (const float*)d_in[6];
    const float* bv = (const float*)d_in[7];
    const float* Wo = (const float*)d_in[8];
    const float* bo = (const float*)d_in[9];
    const float* ln_g = (const float*)d_in[10];
    const float* ln_b = (const float*)d_in[11];
    const float* W1 = (const float*)d_in[12];
    const float* b1 = (const float*)d_in[13];
    const float* W2 = (const float*)d_in[14];
    const float* b2 = (const float*)d_in[15];
    float* out = (float*)d_out;

    float *X, *QKV, *proj, *x1, *ff, *bqkv;
    __half *Xh, *attnh, *x1h, *h1h, *Wqkvh, *Woh, *W1h, *W2h;
    cudaGetSymbolAddress((void**)&X,     g_X);
    cudaGetSymbolAddress((void**)&Xh,    g_Xh);
    cudaGetSymbolAddress((void**)&QKV,   g_QKV);
    cudaGetSymbolAddress((void**)&attnh, g_attnh);
    cudaGetSymbolAddress((void**)&proj,  g_proj);
    cudaGetSymbolAddress((void**)&x1,    g_x1);
    cudaGetSymbolAddress((void**)&x1h,   g_x1h);
    cudaGetSymbolAddress((void**)&h1h,   g_h1h);
    cudaGetSymbolAddress((void**)&ff,    g_ff);
    cudaGetSymbolAddress((void**)&Wqkvh, g_Wqkvh);
    cudaGetSymbolAddress((void**)&bqkv,  g_bqkv);
    cudaGetSymbolAddress((void**)&Woh,   g_Woh);
    cudaGetSymbolAddress((void**)&W1h,   g_W1h);
    cudaGetSymbolAddress((void**)&W2h,   g_W2h);

    const int SMEM_GEMM = NSTAGE * STAGE_BYTES;   // 61440 bytes
    cudaFuncSetAttribute(hgemm_kernel, cudaFuncAttributeMaxDynamicSharedMemorySize, SMEM_GEMM);

    // 0. pack + convert all weights/biases (one launch)
    prep_kernel<<<(786816 + 255) / 256, 256>>>(Wq, Wk, Wv, Wo, W1, W2, bq, bk, bv);

    // 1. stack streams (fp32 + fp16)
    pack_kernel<<<(HALF_M * DIM / 4 + 255) / 256, 256>>>(question, query);

    // 2. fused QKV projection: [16384 x 1536] fp32 out
    hgemm_kernel<<<dim3(QKVN / 128, MTOT / 128), 256, SMEM_GEMM>>>(
        Xh, Wqkvh, bqkv, QKV, DIM, QKVN, 0, 0);

    // 3. shared linear-attention state (split + reduce)
    s_partial_kernel<<<dim3(NB * NH, NSLICE), 256>>>();
    s_reduce_kernel<<<NB * NH, 256>>>();

    // 4. attn = Q @ S (fp16 output)
    qs_kernel<<<dim3(MTOT / 64, NH), 256>>>();

    // 5. output projection (fp32 out)
    hgemm_kernel<<<dim3(DIM / 128, MTOT / 128), 256, SMEM_GEMM>>>(
        attnh, Woh, bo, proj, DIM, DIM, 0, 0);

    // 6. LN1: x1 fp32 + x1h fp16
    ln_kernel<<<MTOT, 128>>>(X, proj, ln_g, ln_b, x1, x1h, 0);

    // 7. FF1 (ReLU fused, fp16 out)
    hgemm_kernel<<<dim3(PF / 128, MTOT / 128), 256, SMEM_GEMM>>>(
        x1h, W1h, b1, h1h, DIM, PF, 1, 1);

    // 8. FF2 (fp32 out)
    hgemm_kernel<<<dim3(DIM / 128, MTOT / 128), 256, SMEM_GEMM>>>(
        h1h, W2h, b2, ff, PF, DIM, 0, 0);

    // 9. LN2 + residual + concat
    ln_kernel<<<MTOT, 128>>>(x1, ff, ln_g, ln_b, out, nullptr, 1);
}